// round 1
// baseline (speedup 1.0000x reference)
#include <cuda_runtime.h>

#define N_NODES 50000
#define N_EDGES 800000
#define HID 128

// ---------------- scratch (static device globals; no allocation) ----------------
__device__ float g_h  [N_NODES*HID];
__device__ float g_agg[N_NODES*HID];
__device__ float g_An [N_NODES*HID];
__device__ float g_Bn [N_NODES*HID];
__device__ int   g_cnt[N_NODES];
__device__ int   g_rowptr[N_NODES+1];
__device__ int   g_fill[N_NODES];
__device__ int   g_csr[N_EDGES];
__device__ float g_Wt [4*256*HID];   // combined [Wl|Wr] transposed per layer: [k][c]
__device__ float g_W1t[264*HID];     // W1 transposed: [k][c]
__device__ float g_W2t[HID*64];      // W2 transposed: [k][c]

// ---------------- CSR build ----------------
__global__ void hist_k(const int* __restrict__ dst){
    int i = blockIdx.x*blockDim.x + threadIdx.x;
    if(i < N_EDGES) atomicAdd(&g_cnt[dst[i]], 1);
}

__global__ void scan_k(){
    __shared__ int s[1024];
    int tid = threadIdx.x;
    int run = 0;
    for(int base = 0; base < N_NODES; base += 1024){
        int i = base + tid;
        int v = (i < N_NODES) ? g_cnt[i] : 0;
        s[tid] = v;
        __syncthreads();
        for(int off = 1; off < 1024; off <<= 1){
            int t = (tid >= off) ? s[tid-off] : 0;
            __syncthreads();
            s[tid] += t;
            __syncthreads();
        }
        if(i < N_NODES) g_rowptr[i] = run + s[tid] - v;   // exclusive
        run += s[1023];
        __syncthreads();
    }
    if(tid == 0) g_rowptr[N_NODES] = run;
}

__global__ void fill_k(const int* __restrict__ src, const int* __restrict__ dst){
    int i = blockIdx.x*blockDim.x + threadIdx.x;
    if(i < N_EDGES){
        int d = dst[i];
        int pos = g_rowptr[d] + atomicAdd(&g_fill[d], 1);
        g_csr[pos] = src[i];
    }
}

// ---------------- weight prep (transposes) ----------------
__global__ void prep_w(const float* __restrict__ W1, const float* __restrict__ W2,
                       const float* __restrict__ Wl, const float* __restrict__ Wr){
    int i = blockIdx.x*blockDim.x + threadIdx.x;
    if(i < 264*HID){ int k = i/HID, c = i%HID; g_W1t[i] = W1[c*264 + k]; }
    if(i < HID*64) { int k = i/64,  c = i%64;  g_W2t[i] = W2[c*HID + k]; }
    if(i < 4*256*HID){
        int l = i/(256*HID); int r = i%(256*HID); int k = r/HID, c = r%HID;
        g_Wt[i] = (k < HID) ? Wl[l*HID*HID + c*HID + k]
                            : Wr[l*HID*HID + c*HID + (k-HID)];
    }
}

// ---------------- input projection h = x @ W_in^T + b_in ----------------
__global__ void inproj_k(const float* __restrict__ x, const float* __restrict__ Win,
                         const float* __restrict__ bin){
    __shared__ float xs[2][16];
    int tid = threadIdx.x;
    int n0 = blockIdx.x*2;
    if(tid < 32){
        int nn = tid/16, k = tid%16;
        int n = n0 + nn;
        xs[nn][k] = (n < N_NODES) ? x[n*16 + k] : 0.f;
    }
    __syncthreads();
    int nn = tid/HID, c = tid%HID;
    int n = n0 + nn;
    if(n < N_NODES){
        float acc = bin[c];
        const float* w = Win + c*16;
        #pragma unroll
        for(int k = 0; k < 16; k++) acc += xs[nn][k]*w[k];
        g_h[n*HID + c] = acc;
    }
}

// ---------------- mean aggregation via CSR gather ----------------
__global__ void agg_k(){
    int warp = threadIdx.x >> 5, lane = threadIdx.x & 31;
    int n = blockIdx.x*4 + warp;
    if(n >= N_NODES) return;
    int beg = g_rowptr[n], end = g_rowptr[n+1];
    float4 acc = make_float4(0.f,0.f,0.f,0.f);
    const float4* hp = reinterpret_cast<const float4*>(g_h);
    for(int j = beg; j < end; j++){
        int s = g_csr[j];
        float4 v = hp[s*32 + lane];
        acc.x += v.x; acc.y += v.y; acc.z += v.z; acc.w += v.w;
    }
    float inv = (end > beg) ? 1.0f/(float)(end - beg) : 0.0f;
    acc.x *= inv; acc.y *= inv; acc.z *= inv; acc.w *= inv;
    reinterpret_cast<float4*>(g_agg)[n*32 + lane] = acc;
}

// ---------------- node GEMM: MODE 0 = layer (K=256, fused LN+ReLU, in-place h)
//                            MODE 1 = plain (K=128, h @ W1t-slice -> An/Bn) ----------------
template<int MODE>
__global__ void __launch_bounds__(256) gemm_k(int widx,
                    const float* __restrict__ bias,
                    const float* __restrict__ lng,
                    const float* __restrict__ lnb){
    __shared__ float As[8][HID];
    __shared__ float Bs[8][HID];
    const int K = (MODE == 0) ? 256 : 128;
    const float* Wt = (MODE == 0) ? (g_Wt + widx*256*HID) : (g_W1t + widx*HID*HID);
    float* out = (MODE == 0) ? g_h : (widx ? g_Bn : g_An);

    int tid = threadIdx.x;
    int m0 = blockIdx.x*128;
    int tx = tid & 15, ty = tid >> 4;

    float acc[8][8];
    #pragma unroll
    for(int i = 0; i < 8; i++)
        #pragma unroll
        for(int j = 0; j < 8; j++) acc[i][j] = 0.f;

    int lm = tid >> 1;          // A-load row 0..127
    int lk = (tid & 1)*4;       // A-load k offset 0/4
    int mA = m0 + lm; if(mA >= N_NODES) mA = N_NODES-1;
    int bk = tid >> 5;          // B-load k row 0..7
    int bn = (tid & 31)*4;      // B-load col

    for(int k0 = 0; k0 < K; k0 += 8){
        const float* Asrc; int kk;
        if(MODE == 0){
            if(k0 < 128){ Asrc = g_agg; kk = k0; }
            else        { Asrc = g_h;   kk = k0 - 128; }
        } else { Asrc = g_h; kk = k0; }
        float4 av = *reinterpret_cast<const float4*>(Asrc + mA*HID + kk + lk);
        float4 bv = *reinterpret_cast<const float4*>(Wt + (k0 + bk)*HID + bn);
        __syncthreads();
        As[lk+0][lm] = av.x; As[lk+1][lm] = av.y; As[lk+2][lm] = av.z; As[lk+3][lm] = av.w;
        *reinterpret_cast<float4*>(&Bs[bk][bn]) = bv;
        __syncthreads();
        #pragma unroll
        for(int k = 0; k < 8; k++){
            float4 a0 = *reinterpret_cast<const float4*>(&As[k][ty*8]);
            float4 a1 = *reinterpret_cast<const float4*>(&As[k][ty*8+4]);
            float4 b0 = *reinterpret_cast<const float4*>(&Bs[k][tx*8]);
            float4 b1 = *reinterpret_cast<const float4*>(&Bs[k][tx*8+4]);
            float a[8] = {a0.x,a0.y,a0.z,a0.w,a1.x,a1.y,a1.z,a1.w};
            float b[8] = {b0.x,b0.y,b0.z,b0.w,b1.x,b1.y,b1.z,b1.w};
            #pragma unroll
            for(int i = 0; i < 8; i++)
                #pragma unroll
                for(int j = 0; j < 8; j++) acc[i][j] += a[i]*b[j];
        }
    }

    if(MODE == 0){
        float breg[8], gg[8], bb[8];
        #pragma unroll
        for(int j = 0; j < 8; j++){
            int n = tx*8 + j;
            breg[j] = bias[n]; gg[j] = lng[n]; bb[j] = lnb[n];
        }
        #pragma unroll
        for(int i = 0; i < 8; i++){
            float s = 0.f, sq = 0.f;
            #pragma unroll
            for(int j = 0; j < 8; j++){
                float v = acc[i][j] + breg[j];
                acc[i][j] = v; s += v; sq += v*v;
            }
            // each row's 128 cols live in one 16-lane group (same ty)
            #pragma unroll
            for(int off = 8; off >= 1; off >>= 1){
                s  += __shfl_xor_sync(0xffffffffu, s,  off, 16);
                sq += __shfl_xor_sync(0xffffffffu, sq, off, 16);
            }
            float mu  = s  * (1.0f/128.0f);
            float var = sq * (1.0f/128.0f) - mu*mu;
            float rs  = rsqrtf(var + 1e-5f);
            int m = m0 + ty*8 + i;
            if(m < N_NODES){
                float o[8];
                #pragma unroll
                for(int j = 0; j < 8; j++){
                    float v = (acc[i][j] - mu)*rs*gg[j] + bb[j];
                    o[j] = fmaxf(v, 0.f);
                }
                float4* d4 = reinterpret_cast<float4*>(g_h + m*HID + tx*8);
                d4[0] = make_float4(o[0],o[1],o[2],o[3]);
                d4[1] = make_float4(o[4],o[5],o[6],o[7]);
            }
        }
    } else {
        #pragma unroll
        for(int i = 0; i < 8; i++){
            int m = m0 + ty*8 + i;
            if(m < N_NODES){
                float4* d4 = reinterpret_cast<float4*>(out + m*HID + tx*8);
                d4[0] = make_float4(acc[i][0],acc[i][1],acc[i][2],acc[i][3]);
                d4[1] = make_float4(acc[i][4],acc[i][5],acc[i][6],acc[i][7]);
            }
        }
    }
}

// ---------------- fused edge head: H1 = relu(An[src]+Bn[dst]+W1c@ea+b1);
//                  out = W3 @ relu(W2 @ H1 + b2) + b3 ----------------
#define EH_H1_STRIDE 132
#define EH_SMEM_FLOATS (128*EH_H1_STRIDE + 128*64 + 8*128 + 128*8 + 128 + 64 + 64)
#define EH_SMEM_BYTES  (EH_SMEM_FLOATS*4 + 2*128*4)

__global__ void __launch_bounds__(256) edge_k(const int* __restrict__ src,
        const int* __restrict__ dst, const float* __restrict__ ea,
        const float* __restrict__ b1, const float* __restrict__ b2,
        const float* __restrict__ W3, const float* __restrict__ b3,
        float* __restrict__ out){
    extern __shared__ float sm[];
    float* H1  = sm;                       // [128][132]
    float* W2s = H1  + 128*EH_H1_STRIDE;   // [128][64]
    float* W1c = W2s + 128*64;             // [8][128]
    float* eas = W1c + 8*128;              // [128][8]
    float* b1s = eas + 128*8;              // [128]
    float* b2s = b1s + 128;                // [64]
    float* W3s = b2s + 64;                 // [64]
    int*   srcs = (int*)(W3s + 64);        // [128]
    int*   dsts = srcs + 128;              // [128]

    int tid = threadIdx.x;
    int e0 = blockIdx.x*128;

    if(tid < 128){ srcs[tid] = src[e0+tid]; dsts[tid] = dst[e0+tid]; b1s[tid] = b1[tid]; }
    else if(tid < 192){ int j = tid-128; b2s[j] = b2[j]; W3s[j] = W3[j]; }
    {   // edge_attr: 128*8 floats
        int m = tid >> 1, k = (tid & 1)*4;
        *reinterpret_cast<float4*>(&eas[m*8 + k]) =
            *reinterpret_cast<const float4*>(&ea[(e0+m)*8 + k]);
    }
    {   // W1c rows 256..263 of W1t
        int idx = tid*4;
        *reinterpret_cast<float4*>(&W1c[idx]) =
            *reinterpret_cast<const float4*>(&g_W1t[256*HID + idx]);
    }
    #pragma unroll
    for(int r = 0; r < 8; r++){            // W2t: 8192 floats
        int idx = r*1024 + tid*4;
        *reinterpret_cast<float4*>(&W2s[idx]) =
            *reinterpret_cast<const float4*>(&g_W2t[idx]);
    }
    __syncthreads();

    // phase 1: build H1[m][0..127] ; thread handles half a row (64 cols)
    {
        int m = tid >> 1, half = tid & 1, n0 = half*64;
        int s = srcs[m], d = dsts[m];
        float e8[8];
        #pragma unroll
        for(int k = 0; k < 8; k++) e8[k] = eas[m*8 + k];
        const float* Ap = g_An + s*HID + n0;
        const float* Bp = g_Bn + d*HID + n0;
        #pragma unroll
        for(int j4 = 0; j4 < 64; j4 += 4){
            float4 a  = *reinterpret_cast<const float4*>(Ap + j4);
            float4 b  = *reinterpret_cast<const float4*>(Bp + j4);
            float4 bb = *reinterpret_cast<const float4*>(&b1s[n0 + j4]);
            float vx = a.x + b.x + bb.x;
            float vy = a.y + b.y + bb.y;
            float vz = a.z + b.z + bb.z;
            float vw = a.w + b.w + bb.w;
            #pragma unroll
            for(int k = 0; k < 8; k++){
                float4 w = *reinterpret_cast<const float4*>(&W1c[k*HID + n0 + j4]);
                vx += e8[k]*w.x; vy += e8[k]*w.y; vz += e8[k]*w.z; vw += e8[k]*w.w;
            }
            float* hrow = &H1[m*EH_H1_STRIDE + n0 + j4];
            hrow[0] = fmaxf(vx,0.f); hrow[1] = fmaxf(vy,0.f);
            hrow[2] = fmaxf(vz,0.f); hrow[3] = fmaxf(vw,0.f);
        }
    }
    __syncthreads();

    // phase 2: [128 edges x 64] = H1 @ W2t ; then relu(+b2) . W3 + b3
    int tx = tid & 7, ty = tid >> 3;       // tx: 8 col-groups, ty: 32 row-groups of 4
    float c2[4][8];
    #pragma unroll
    for(int i = 0; i < 4; i++)
        #pragma unroll
        for(int j = 0; j < 8; j++) c2[i][j] = 0.f;

    const float* h0 = &H1[(ty*4)*EH_H1_STRIDE];
    #pragma unroll 4
    for(int k = 0; k < 128; k++){
        float a0 = h0[0*EH_H1_STRIDE + k];
        float a1 = h0[1*EH_H1_STRIDE + k];
        float a2 = h0[2*EH_H1_STRIDE + k];
        float a3 = h0[3*EH_H1_STRIDE + k];
        float4 w0 = *reinterpret_cast<const float4*>(&W2s[k*64 + tx*8]);
        float4 w1 = *reinterpret_cast<const float4*>(&W2s[k*64 + tx*8 + 4]);
        float w[8] = {w0.x,w0.y,w0.z,w0.w,w1.x,w1.y,w1.z,w1.w};
        float a[4] = {a0,a1,a2,a3};
        #pragma unroll
        for(int i = 0; i < 4; i++)
            #pragma unroll
            for(int j = 0; j < 8; j++) c2[i][j] += a[i]*w[j];
    }

    float b2r[8], w3r[8];
    #pragma unroll
    for(int j = 0; j < 8; j++){ b2r[j] = b2s[tx*8+j]; w3r[j] = W3s[tx*8+j]; }
    float bias3 = b3[0];
    #pragma unroll
    for(int i = 0; i < 4; i++){
        float p = 0.f;
        #pragma unroll
        for(int j = 0; j < 8; j++) p += fmaxf(c2[i][j] + b2r[j], 0.f)*w3r[j];
        p += __shfl_xor_sync(0xffffffffu, p, 4, 8);
        p += __shfl_xor_sync(0xffffffffu, p, 2, 8);
        p += __shfl_xor_sync(0xffffffffu, p, 1, 8);
        if(tx == 0) out[e0 + ty*4 + i] = p + bias3;
    }
}

// ---------------- launch ----------------
extern "C" void kernel_launch(void* const* d_in, const int* in_sizes, int n_in,
                              void* d_out, int out_size){
    const float* x   = (const float*)d_in[0];
    const int*   ei  = (const int*)  d_in[1];
    const float* ea  = (const float*)d_in[2];
    const float* Win = (const float*)d_in[3];
    const float* bin = (const float*)d_in[4];
    const float* Wl  = (const float*)d_in[5];
    const float* bl  = (const float*)d_in[6];
    const float* Wr  = (const float*)d_in[7];
    const float* lng = (const float*)d_in[8];
    const float* lnb = (const float*)d_in[9];
    const float* W1  = (const float*)d_in[10];
    const float* b1  = (const float*)d_in[11];
    const float* W2  = (const float*)d_in[12];
    const float* b2  = (const float*)d_in[13];
    const float* W3  = (const float*)d_in[14];
    const float* b3  = (const float*)d_in[15];
    const int* src = ei;
    const int* dst = ei + N_EDGES;

    void* p;
    cudaGetSymbolAddress(&p, g_cnt);  cudaMemsetAsync(p, 0, N_NODES*sizeof(int));
    cudaGetSymbolAddress(&p, g_fill); cudaMemsetAsync(p, 0, N_NODES*sizeof(int));

    hist_k<<<(N_EDGES+255)/256, 256>>>(dst);
    scan_k<<<1, 1024>>>();
    fill_k<<<(N_EDGES+255)/256, 256>>>(src, dst);
    prep_w<<<(4*256*HID+255)/256, 256>>>(W1, W2, Wl, Wr);
    inproj_k<<<(N_NODES+1)/2, 256>>>(x, Win, bin);

    const int gemm_blocks = (N_NODES + 127)/128;
    for(int l = 0; l < 4; l++){
        agg_k<<<(N_NODES+3)/4, 128>>>();
        gemm_k<0><<<gemm_blocks, 256>>>(l, bl + l*HID, lng + l*HID, lnb + l*HID);
    }
    gemm_k<1><<<gemm_blocks, 256>>>(0, nullptr, nullptr, nullptr);  // An
    gemm_k<1><<<gemm_blocks, 256>>>(1, nullptr, nullptr, nullptr);  // Bn

    cudaFuncSetAttribute(edge_k, cudaFuncAttributeMaxDynamicSharedMemorySize, EH_SMEM_BYTES);
    edge_k<<<N_EDGES/128, 256, EH_SMEM_BYTES>>>(src, dst, ea, b1, b2, W3, b3, (float*)d_out);
}

// round 3
// speedup vs baseline: 1.5898x; 1.5898x over previous
#include <cuda_runtime.h>
#include <cstdint>

#define N_NODES 50000
#define N_EDGES 800000
#define HID 128

// ---------------- scratch ----------------
__device__ float g_h  [N_NODES*HID];
__device__ float g_agg[N_NODES*HID];
__device__ float g_An [N_NODES*HID];
__device__ float g_Bn [N_NODES*HID];
__device__ int   g_cnt[N_NODES];
__device__ int   g_rowptr[N_NODES+1];
__device__ int   g_fill[N_NODES];
__device__ int   g_csr[N_EDGES];
__device__ float g_W1c[8*HID];       // W1 cols 256..263 transposed: [k][c]
__device__ float g_W2t[HID*64];      // W2 transposed: [k][c]

// ---------------- tf32 mma helpers ----------------
__device__ __forceinline__ uint32_t f2tf(float f){
    uint32_t r;
    asm("cvt.rna.tf32.f32 %0, %1;" : "=r"(r) : "f"(f));
    return r;
}
__device__ __forceinline__ void mma_tf32(float* c, const uint32_t* a, uint32_t b0, uint32_t b1){
    asm volatile("mma.sync.aligned.m16n8k8.row.col.f32.tf32.tf32.f32 "
        "{%0,%1,%2,%3}, {%4,%5,%6,%7}, {%8,%9}, {%0,%1,%2,%3};"
        : "+f"(c[0]), "+f"(c[1]), "+f"(c[2]), "+f"(c[3])
        : "r"(a[0]), "r"(a[1]), "r"(a[2]), "r"(a[3]), "r"(b0), "r"(b1));
}

// ---------------- CSR build ----------------
__global__ void hist_k(const int* __restrict__ dst){
    int i = blockIdx.x*blockDim.x + threadIdx.x;
    if(i < N_EDGES) atomicAdd(&g_cnt[dst[i]], 1);
}

__global__ void scan_k(){
    __shared__ int s[1024];
    int tid = threadIdx.x;
    int run = 0;
    for(int base = 0; base < N_NODES; base += 1024){
        int i = base + tid;
        int v = (i < N_NODES) ? g_cnt[i] : 0;
        s[tid] = v;
        __syncthreads();
        for(int off = 1; off < 1024; off <<= 1){
            int t = (tid >= off) ? s[tid-off] : 0;
            __syncthreads();
            s[tid] += t;
            __syncthreads();
        }
        if(i < N_NODES) g_rowptr[i] = run + s[tid] - v;
        run += s[1023];
        __syncthreads();
    }
    if(tid == 0) g_rowptr[N_NODES] = run;
}

__global__ void fill_k(const int* __restrict__ src, const int* __restrict__ dst){
    int i = blockIdx.x*blockDim.x + threadIdx.x;
    if(i < N_EDGES){
        int d = dst[i];
        int pos = g_rowptr[d] + atomicAdd(&g_fill[d], 1);
        g_csr[pos] = src[i];
    }
}

// ---------------- weight prep ----------------
__global__ void prep_w(const float* __restrict__ W1, const float* __restrict__ W2){
    int i = blockIdx.x*blockDim.x + threadIdx.x;
    if(i < 8*HID)  { int k = i/HID, c = i%HID; g_W1c[i] = W1[c*264 + 256 + k]; }
    if(i < HID*64) { int k = i/64,  c = i%64;  g_W2t[i] = W2[c*HID + k]; }
}

// ---------------- input projection ----------------
__global__ void inproj_k(const float* __restrict__ x, const float* __restrict__ Win,
                         const float* __restrict__ bin){
    __shared__ float xs[2][16];
    int tid = threadIdx.x;
    int n0 = blockIdx.x*2;
    if(tid < 32){
        int nn = tid/16, k = tid%16;
        int n = n0 + nn;
        xs[nn][k] = (n < N_NODES) ? x[n*16 + k] : 0.f;
    }
    __syncthreads();
    int nn = tid/HID, c = tid%HID;
    int n = n0 + nn;
    if(n < N_NODES){
        float acc = bin[c];
        const float* w = Win + c*16;
        #pragma unroll
        for(int k = 0; k < 16; k++) acc += xs[nn][k]*w[k];
        g_h[n*HID + c] = acc;
    }
}

// ---------------- mean aggregation (CSR gather, MLP=4) ----------------
__global__ void agg_k(){
    int warp = threadIdx.x >> 5, lane = threadIdx.x & 31;
    int n = blockIdx.x*8 + warp;
    if(n >= N_NODES) return;
    int beg = g_rowptr[n], end = g_rowptr[n+1];
    float4 acc = make_float4(0.f,0.f,0.f,0.f);
    const float4* hp = reinterpret_cast<const float4*>(g_h);
    int j = beg;
    for(; j + 4 <= end; j += 4){
        int s0 = g_csr[j], s1 = g_csr[j+1], s2 = g_csr[j+2], s3 = g_csr[j+3];
        float4 v0 = hp[s0*32 + lane];
        float4 v1 = hp[s1*32 + lane];
        float4 v2 = hp[s2*32 + lane];
        float4 v3 = hp[s3*32 + lane];
        acc.x += (v0.x+v1.x) + (v2.x+v3.x);
        acc.y += (v0.y+v1.y) + (v2.y+v3.y);
        acc.z += (v0.z+v1.z) + (v2.z+v3.z);
        acc.w += (v0.w+v1.w) + (v2.w+v3.w);
    }
    for(; j < end; j++){
        int s = g_csr[j];
        float4 v = hp[s*32 + lane];
        acc.x += v.x; acc.y += v.y; acc.z += v.z; acc.w += v.w;
    }
    float inv = (end > beg) ? 1.0f/(float)(end - beg) : 0.0f;
    acc.x *= inv; acc.y *= inv; acc.z *= inv; acc.w *= inv;
    reinterpret_cast<float4*>(g_agg)[n*32 + lane] = acc;
}

// ---------------- tf32 mma.sync node GEMM ----------------
// MODE 0: C = [agg|h] @ [Wl|Wr]^T (K=256) + bias, LN, ReLU -> g_h
// MODE 1: C = h @ W1[:, y*128 : y*128+128]^T (K=128) -> g_An / g_Bn
template<int MODE>
__global__ void __launch_bounds__(256) gemm_m(
        const float* __restrict__ Wa, const float* __restrict__ Wb,
        const float* __restrict__ bias, const float* __restrict__ lng,
        const float* __restrict__ lnb){
    __shared__ uint32_t As[128*36];
    __shared__ uint32_t Bs[128*36];
    __shared__ float prm[384];
    __shared__ float ps[256], pq[256];

    int tid = threadIdx.x;
    int lane = tid & 31, wid = tid >> 5;
    int g = lane >> 2, t = lane & 3;
    int wy = wid & 3, wx = wid >> 2;
    int m0 = blockIdx.x*128;

    float c[2][8][4];
    #pragma unroll
    for(int mi = 0; mi < 2; mi++)
        #pragma unroll
        for(int nf = 0; nf < 8; nf++)
            #pragma unroll
            for(int j = 0; j < 4; j++) c[mi][nf][j] = 0.f;

    if(MODE == 0 && tid < 128){
        prm[tid] = bias[tid]; prm[128+tid] = lng[tid]; prm[256+tid] = lnb[tid];
    }

    const int NCH = (MODE == 0) ? 8 : 4;
    float4 sa[4], sb[4];

    // prefetch chunk 0
    {
        const float* Ap = (MODE == 0) ? g_agg : g_h;
        #pragma unroll
        for(int i = 0; i < 4; i++){
            int s = tid + i*256;
            int r = s >> 3, c4 = (s & 7)*4;
            int mr = m0 + r; if(mr >= N_NODES) mr = N_NODES-1;
            sa[i] = *(const float4*)(Ap + mr*128 + c4);
            const float* Bp = (MODE == 0) ? (Wa + r*128 + c4)
                                          : (Wa + r*264 + blockIdx.y*128 + c4);
            sb[i] = *(const float4*)Bp;
        }
    }

    for(int ch = 0; ch < NCH; ch++){
        // store staged chunk to smem (cvt tf32)
        #pragma unroll
        for(int i = 0; i < 4; i++){
            int s = tid + i*256;
            int r = s >> 3, c4 = (s & 7)*4;
            uint32_t* d = As + r*36 + c4;
            d[0] = f2tf(sa[i].x); d[1] = f2tf(sa[i].y); d[2] = f2tf(sa[i].z); d[3] = f2tf(sa[i].w);
            uint32_t* e = Bs + r*36 + c4;
            e[0] = f2tf(sb[i].x); e[1] = f2tf(sb[i].y); e[2] = f2tf(sb[i].z); e[3] = f2tf(sb[i].w);
        }
        __syncthreads();
        // prefetch next chunk
        if(ch + 1 < NCH){
            int nc = ch + 1;
            const float* Ap = (MODE == 0 && nc < 4) ? g_agg : g_h;
            int kc = (MODE == 0) ? (nc & 3)*32 : nc*32;
            #pragma unroll
            for(int i = 0; i < 4; i++){
                int s = tid + i*256;
                int r = s >> 3, c4 = (s & 7)*4;
                int mr = m0 + r; if(mr >= N_NODES) mr = N_NODES-1;
                sa[i] = *(const float4*)(Ap + mr*128 + kc + c4);
                const float* Bp;
                if(MODE == 0){
                    const float* W = (nc < 4) ? Wa : Wb;
                    Bp = W + r*128 + (nc & 3)*32 + c4;
                } else {
                    Bp = Wa + r*264 + blockIdx.y*128 + nc*32 + c4;
                }
                sb[i] = *(const float4*)Bp;
            }
        }
        // mma over this chunk
        const uint32_t* a_sm = As + (wy*32 + g)*36 + t;
        const uint32_t* b_sm = Bs + (wx*64 + g)*36 + t;
        #pragma unroll
        for(int kk = 0; kk < 4; kk++){
            int k0 = kk*8;
            uint32_t a[2][4];
            #pragma unroll
            for(int mi = 0; mi < 2; mi++){
                const uint32_t* p = a_sm + mi*16*36 + k0;
                a[mi][0] = p[0]; a[mi][1] = p[8*36]; a[mi][2] = p[4]; a[mi][3] = p[8*36+4];
            }
            #pragma unroll
            for(int nf = 0; nf < 8; nf++){
                const uint32_t* q = b_sm + nf*8*36 + k0;
                uint32_t b0 = q[0], b1 = q[4];
                mma_tf32(c[0][nf], a[0], b0, b1);
                mma_tf32(c[1][nf], a[1], b0, b1);
            }
        }
        __syncthreads();
    }

    int colb = wx*64;
    if(MODE == 0){
        // bias add + partial row stats
        #pragma unroll
        for(int mi = 0; mi < 2; mi++)
            #pragma unroll
            for(int rr = 0; rr < 2; rr++){
                float s = 0.f, sq = 0.f;
                #pragma unroll
                for(int nf = 0; nf < 8; nf++)
                    #pragma unroll
                    for(int j = 0; j < 2; j++){
                        int col = colb + nf*8 + 2*t + j;
                        float v = c[mi][nf][rr*2+j] + prm[col];
                        c[mi][nf][rr*2+j] = v;
                        s += v; sq += v*v;
                    }
                s  += __shfl_xor_sync(0xffffffffu, s, 1);
                s  += __shfl_xor_sync(0xffffffffu, s, 2);
                sq += __shfl_xor_sync(0xffffffffu, sq, 1);
                sq += __shfl_xor_sync(0xffffffffu, sq, 2);
                if(t == 0){
                    int row = wy*32 + mi*16 + rr*8 + g;
                    ps[wx*128 + row] = s;
                    pq[wx*128 + row] = sq;
                }
            }
        __syncthreads();
        #pragma unroll
        for(int mi = 0; mi < 2; mi++)
            #pragma unroll
            for(int rr = 0; rr < 2; rr++){
                int row = wy*32 + mi*16 + rr*8 + g;
                int m = m0 + row;
                float st  = ps[row] + ps[128+row];
                float sqt = pq[row] + pq[128+row];
                float mu  = st * (1.0f/128.0f);
                float var = sqt * (1.0f/128.0f) - mu*mu;
                float rs  = rsqrtf(var + 1e-5f);
                if(m < N_NODES){
                    #pragma unroll
                    for(int nf = 0; nf < 8; nf++){
                        int col = colb + nf*8 + 2*t;
                        float2 o;
                        o.x = fmaxf((c[mi][nf][rr*2+0]-mu)*rs*prm[128+col]   + prm[256+col],   0.f);
                        o.y = fmaxf((c[mi][nf][rr*2+1]-mu)*rs*prm[128+col+1] + prm[256+col+1], 0.f);
                        *(float2*)(g_h + m*128 + col) = o;
                    }
                }
            }
    } else {
        float* out = blockIdx.y ? g_Bn : g_An;
        #pragma unroll
        for(int mi = 0; mi < 2; mi++)
            #pragma unroll
            for(int rr = 0; rr < 2; rr++){
                int row = wy*32 + mi*16 + rr*8 + g;
                int m = m0 + row;
                if(m < N_NODES){
                    #pragma unroll
                    for(int nf = 0; nf < 8; nf++){
                        int col = colb + nf*8 + 2*t;
                        *(float2*)(out + m*128 + col) =
                            make_float2(c[mi][nf][rr*2+0], c[mi][nf][rr*2+1]);
                    }
                }
            }
    }
}

// ---------------- fused edge head ----------------
// H1 = relu(An[src]+Bn[dst]+W1c.ea+b1)  (tf32-rounded into smem)
// phase2: tf32 mma [128x64] = H1 @ W2t ; relu(+b2).W3 + b3
#define EH_H1_STRIDE 132
#define EH_W2_STRIDE 72
#define EH_SMEM_FLOATS (128*EH_H1_STRIDE + 128*EH_W2_STRIDE + 8*128 + 128*8 + 128 + 64 + 64)
#define EH_SMEM_BYTES  (EH_SMEM_FLOATS*4 + 2*128*4)

__global__ void __launch_bounds__(256) edge_k(const int* __restrict__ src,
        const int* __restrict__ dst, const float* __restrict__ ea,
        const float* __restrict__ b1, const float* __restrict__ b2,
        const float* __restrict__ W3, const float* __restrict__ b3,
        float* __restrict__ out){
    extern __shared__ float smf[];
    float* H1  = smf;                          // [128][132]
    float* W2s = H1  + 128*EH_H1_STRIDE;       // [128 k][72]
    float* W1c = W2s + 128*EH_W2_STRIDE;       // [8][128]
    float* eas = W1c + 8*128;                  // [128][8]
    float* b1s = eas + 128*8;                  // [128]
    float* b2s = b1s + 128;                    // [64]
    float* W3s = b2s + 64;                     // [64]
    int*   srcs = (int*)(W3s + 64);            // [128]
    int*   dsts = srcs + 128;                  // [128]

    int tid = threadIdx.x;
    int e0 = blockIdx.x*128;

    if(tid < 128){ srcs[tid] = src[e0+tid]; dsts[tid] = dst[e0+tid]; b1s[tid] = b1[tid]; }
    else if(tid < 192){ int j = tid-128; b2s[j] = b2[j]; W3s[j] = W3[j]; }
    {
        int m = tid >> 1, k = (tid & 1)*4;
        *reinterpret_cast<float4*>(&eas[m*8 + k]) =
            *reinterpret_cast<const float4*>(&ea[(e0+m)*8 + k]);
    }
    {
        int idx = tid*4;
        *reinterpret_cast<float4*>(&W1c[idx]) =
            *reinterpret_cast<const float4*>(&g_W1c[idx]);
    }
    {   // W2: [k][64] -> smem [k][72], cvt tf32
        uint32_t* W2u = (uint32_t*)W2s;
        #pragma unroll
        for(int r = 0; r < 8; r++){
            int idx = r*1024 + tid*4;
            int k = idx >> 6, n = idx & 63;
            float4 v = *reinterpret_cast<const float4*>(&g_W2t[idx]);
            uint32_t* d = W2u + k*EH_W2_STRIDE + n;
            d[0] = f2tf(v.x); d[1] = f2tf(v.y); d[2] = f2tf(v.z); d[3] = f2tf(v.w);
        }
    }
    __syncthreads();

    // phase 1
    {
        int m = tid >> 1, halfc = tid & 1, n0 = halfc*64;
        int s = srcs[m], dd = dsts[m];
        float e8[8];
        #pragma unroll
        for(int k = 0; k < 8; k++) e8[k] = eas[m*8 + k];
        const float* Ap = g_An + s*HID + n0;
        const float* Bp = g_Bn + dd*HID + n0;
        uint32_t* hrowu = (uint32_t*)&H1[m*EH_H1_STRIDE + n0];
        #pragma unroll
        for(int j4 = 0; j4 < 64; j4 += 4){
            float4 a  = *reinterpret_cast<const float4*>(Ap + j4);
            float4 b  = *reinterpret_cast<const float4*>(Bp + j4);
            float4 bb = *reinterpret_cast<const float4*>(&b1s[n0 + j4]);
            float vx = a.x + b.x + bb.x;
            float vy = a.y + b.y + bb.y;
            float vz = a.z + b.z + bb.z;
            float vw = a.w + b.w + bb.w;
            #pragma unroll
            for(int k = 0; k < 8; k++){
                float4 w = *reinterpret_cast<const float4*>(&W1c[k*HID + n0 + j4]);
                vx += e8[k]*w.x; vy += e8[k]*w.y; vz += e8[k]*w.z; vw += e8[k]*w.w;
            }
            hrowu[j4+0] = f2tf(fmaxf(vx,0.f));
            hrowu[j4+1] = f2tf(fmaxf(vy,0.f));
            hrowu[j4+2] = f2tf(fmaxf(vz,0.f));
            hrowu[j4+3] = f2tf(fmaxf(vw,0.f));
        }
    }
    __syncthreads();

    // phase 2: mma
    int lane = tid & 31, wid = tid >> 5;
    int g = lane >> 2, t = lane & 3;
    const uint32_t* H1u = (const uint32_t*)H1;
    const uint32_t* W2u = (const uint32_t*)W2s;

    float c2[8][4];
    #pragma unroll
    for(int nf = 0; nf < 8; nf++)
        #pragma unroll
        for(int j = 0; j < 4; j++) c2[nf][j] = 0.f;

    const uint32_t* a_sm = H1u + (wid*16 + g)*EH_H1_STRIDE + t;
    const uint32_t* b_sm = W2u + t*EH_W2_STRIDE + g;
    #pragma unroll
    for(int kk = 0; kk < 16; kk++){
        int k0 = kk*8;
        uint32_t a[4];
        const uint32_t* p = a_sm + k0;
        a[0] = p[0]; a[1] = p[8*EH_H1_STRIDE]; a[2] = p[4]; a[3] = p[8*EH_H1_STRIDE+4];
        const uint32_t* q = b_sm + k0*EH_W2_STRIDE;
        #pragma unroll
        for(int nf = 0; nf < 8; nf++){
            uint32_t b0 = q[nf*8];
            uint32_t b1v = q[4*EH_W2_STRIDE + nf*8];
            mma_tf32(c2[nf], a, b0, b1v);
        }
    }

    float bias3 = b3[0];
    #pragma unroll
    for(int rr = 0; rr < 2; rr++){
        float p = 0.f;
        #pragma unroll
        for(int nf = 0; nf < 8; nf++)
            #pragma unroll
            for(int j = 0; j < 2; j++){
                int col = nf*8 + 2*t + j;
                p += fmaxf(c2[nf][rr*2+j] + b2s[col], 0.f) * W3s[col];
            }
        p += __shfl_xor_sync(0xffffffffu, p, 1);
        p += __shfl_xor_sync(0xffffffffu, p, 2);
        if(t == 0) out[e0 + wid*16 + rr*8 + g] = p + bias3;
    }
}

// ---------------- launch ----------------
extern "C" void kernel_launch(void* const* d_in, const int* in_sizes, int n_in,
                              void* d_out, int out_size){
    const float* x   = (const float*)d_in[0];
    const int*   ei  = (const int*)  d_in[1];
    const float* ea  = (const float*)d_in[2];
    const float* Win = (const float*)d_in[3];
    const float* bin = (const float*)d_in[4];
    const float* Wl  = (const float*)d_in[5];
    const float* bl  = (const float*)d_in[6];
    const float* Wr  = (const float*)d_in[7];
    const float* lng = (const float*)d_in[8];
    const float* lnb = (const float*)d_in[9];
    const float* W1  = (const float*)d_in[10];
    const float* b1  = (const float*)d_in[11];
    const float* W2  = (const float*)d_in[12];
    const float* b2  = (const float*)d_in[13];
    const float* W3  = (const float*)d_in[14];
    const float* b3  = (const float*)d_in[15];
    const int* src = ei;
    const int* dst = ei + N_EDGES;

    void* p;
    cudaGetSymbolAddress(&p, g_cnt);  cudaMemsetAsync(p, 0, N_NODES*sizeof(int));
    cudaGetSymbolAddress(&p, g_fill); cudaMemsetAsync(p, 0, N_NODES*sizeof(int));

    hist_k<<<(N_EDGES+255)/256, 256>>>(dst);
    scan_k<<<1, 1024>>>();
    fill_k<<<(N_EDGES+255)/256, 256>>>(src, dst);
    prep_w<<<((HID*64)+255)/256, 256>>>(W1, W2);
    inproj_k<<<(N_NODES+1)/2, 256>>>(x, Win, bin);

    static bool attr_done = false;
    if(!attr_done){
        cudaFuncSetAttribute(edge_k, cudaFuncAttributeMaxDynamicSharedMemorySize, EH_SMEM_BYTES);
        attr_done = true;
    }

    const int gb = (N_NODES + 127)/128;  // 391
    for(int l = 0; l < 4; l++){
        agg_k<<<(N_NODES+7)/8, 256>>>();
        gemm_m<0><<<gb, 256>>>(Wl + l*HID*HID, Wr + l*HID*HID,
                               bl + l*HID, lng + l*HID, lnb + l*HID);
    }
    gemm_m<1><<<dim3(gb,2), 256>>>(W1, nullptr, nullptr, nullptr, nullptr);

    edge_k<<<N_EDGES/128, 256, EH_SMEM_BYTES>>>(src, dst, ea, b1, b2, W3, b3, (float*)d_out);
}